// round 2
// baseline (speedup 1.0000x reference)
#include <cuda_runtime.h>

#define GRID9   9
#define SN      81          // STATE_NUM
#define HID     32
#define WARPS   8
#define THREADS (WARPS * 32)

__global__ __launch_bounds__(THREADS)
void gdvpn_kernel(const float* __restrict__ obs,     // (B, 2*SN)
                  const float* __restrict__ A,       // (B, SN, SN) action_count
                  const float* __restrict__ W1,      // (SN, HID)
                  const float* __restrict__ W2,      // (HID, HID)
                  const float* __restrict__ W3,      // (HID, 1)
                  const float* __restrict__ b3,      // (1,)
                  float* __restrict__ out,           // [sym B | ir B | nr B | nsc B*SN]
                  int B)
{
    __shared__ float sW1[SN * HID];     // 10368 B
    __shared__ float sW2[HID * HID];    //  4096 B
    __shared__ float sW3[HID];
    __shared__ float sNsc[WARPS][96];   // padded
    __shared__ float sH1[WARPS][HID];

    const int tid = threadIdx.x;
    for (int k = tid; k < SN * HID; k += THREADS) sW1[k] = W1[k];
    for (int k = tid; k < HID * HID; k += THREADS) sW2[k] = W2[k];
    if (tid < HID) sW3[tid] = W3[tid];
    __syncthreads();

    const int warp = tid >> 5;
    const int lane = tid & 31;
    const int b = blockIdx.x * WARPS + warp;
    if (b >= B) return;

    const float* __restrict__ Ab  = A + (size_t)b * (SN * SN);
    const float* __restrict__ dem = obs + (size_t)b * (2 * SN) + SN;

    // ------- Phase 1: gather/segment-sum (arithmetic form) + immediate reward -------
    // nsc[i] = A[i][i] + A[i-9][i] + A[i+9][i] + A[i-1][i] + A[i+1][i]  (bounds-checked)
    float ir = 0.0f;
    #pragma unroll
    for (int t = 0; t < 3; ++t) {
        const int i = lane + 32 * t;
        if (i < SN) {
            const int r = i / GRID9;
            const int c = i - r * GRID9;
            float v = __ldg(&Ab[i * SN + i]);
            if (r > 0)         v += __ldg(&Ab[(i - GRID9) * SN + i]);
            if (r < GRID9 - 1) v += __ldg(&Ab[(i + GRID9) * SN + i]);
            if (c > 0)         v += __ldg(&Ab[(i - 1) * SN + i]);
            if (c < GRID9 - 1) v += __ldg(&Ab[(i + 1) * SN + i]);
            ir += fminf(v, __ldg(&dem[i]));
            sNsc[warp][i] = v;
            out[(size_t)3 * B + (size_t)b * SN + i] = v;   // nsc output
        }
    }
    #pragma unroll
    for (int off = 16; off; off >>= 1) ir += __shfl_xor_sync(0xffffffffu, ir, off);
    __syncwarp();

    // ------- Phase 2: h1 = relu(nsc @ W1) ; lane owns hidden unit `lane` -------
    float h1 = 0.0f;
    #pragma unroll 3
    for (int i = 0; i < SN; ++i)
        h1 = fmaf(sNsc[warp][i], sW1[i * HID + lane], h1);
    h1 = fmaxf(h1, 0.0f);
    sH1[warp][lane] = h1;
    __syncwarp();

    // ------- Phase 3: h2 = relu(h1 @ W2) ; next_return = h2 @ W3 + b3 -------
    float h2 = 0.0f;
    #pragma unroll
    for (int k = 0; k < HID; ++k)
        h2 = fmaf(sH1[warp][k], sW2[k * HID + lane], h2);
    h2 = fmaxf(h2, 0.0f);

    float nr = h2 * sW3[lane];
    #pragma unroll
    for (int off = 16; off; off >>= 1) nr += __shfl_xor_sync(0xffffffffu, nr, off);

    if (lane == 0) {
        nr += __ldg(&b3[0]);
        out[b]                 = ir + nr;   // symbolic_val
        out[(size_t)B + b]     = ir;        // immediate_reward
        out[(size_t)2 * B + b] = nr;        // next_return
    }
}

extern "C" void kernel_launch(void* const* d_in, const int* in_sizes, int n_in,
                              void* d_out, int out_size)
{
    const float* obs = (const float*)d_in[0];
    const float* A   = (const float*)d_in[1];
    const float* W1  = (const float*)d_in[2];
    const float* W2  = (const float*)d_in[3];
    const float* W3  = (const float*)d_in[4];
    const float* b3  = (const float*)d_in[5];
    // d_in[6..8] = inflow_src/act/seg: structure is compile-time known, unused.

    const int B = in_sizes[0] / (2 * SN);
    float* out = (float*)d_out;

    const int blocks = (B + WARPS - 1) / WARPS;
    gdvpn_kernel<<<blocks, THREADS>>>(obs, A, W1, W2, W3, b3, out, B);
}